// round 5
// baseline (speedup 1.0000x reference)
#include <cuda_runtime.h>

// TropicalLeNet: 3 stage kernels, batch split into 2 halves pipelined on
// 2 streams (capturable fork/join). Per-image dependency chain is narrow,
// so half-B's conv1 overlaps half-A's conv2, etc.

#define BMAX 256

__device__ float g_p1[BMAX * 6 * 14 * 16];  // [b][c][14][16] (cols 14-15 pad)
__device__ float g_p2[BMAX * 400];          // [b][oc*25+sp]

// ---------------------------------------------------------------------------
// Kernel A: min-plus conv1 (C=1 -> O=6, k=5, pad=2) + 2x2 avgpool.
// grid (2, Bh): CTA = 3 output channels of one image. Single staging pass.
// ---------------------------------------------------------------------------
__global__ void __launch_bounds__(224)
conv1_kernel(const float* __restrict__ input, const float* __restrict__ w1,
             int b0)
{
    const int cg = blockIdx.x, b = blockIdx.y + b0;
    const int tid = threadIdx.x;

    __shared__ __align__(16) float xp[32 * 32];
    __shared__ __align__(16) float ws[3 * 28];

    const float* inb = input + b * 784;
    #pragma unroll
    for (int k = 0; k < 5; k++) {
        int i = tid + 224 * k;
        if (i < 1024) {
            int h = i >> 5, w = i & 31;
            bool in = (h >= 2) && (h < 30) && (w >= 2) && (w < 30);
            xp[i] = in ? inb[(h - 2) * 28 + (w - 2)] : 0.0f;
        }
    }
    if (tid < 75) ws[(tid / 25) * 28 + tid % 25] = w1[cg * 75 + tid];
    __syncthreads();

    if (tid < 196) {
        const int i = tid / 14, j = tid % 14;
        const int base = i * 64 + 2 * j;

        float win[6][6];
        #pragma unroll
        for (int u = 0; u < 6; u++) {
            const float2* r = (const float2*)&xp[base + u * 32];
            float2 a = r[0], bb = r[1], c2 = r[2];
            win[u][0] = a.x;  win[u][1] = a.y;
            win[u][2] = bb.x; win[u][3] = bb.y;
            win[u][4] = c2.x; win[u][5] = c2.y;
        }

        #pragma unroll 1
        for (int cc = 0; cc < 3; cc++) {
            float wr[25];
            {
                const float4* wq = (const float4*)&ws[cc * 28];
                #pragma unroll
                for (int q = 0; q < 6; q++) {
                    float4 v = wq[q];
                    wr[4 * q]     = v.x; wr[4 * q + 1] = v.y;
                    wr[4 * q + 2] = v.z; wr[4 * q + 3] = v.w;
                }
                wr[24] = ws[cc * 28 + 24];
            }

            float m00 = win[0][0] + wr[0];
            float m01 = win[0][1] + wr[0];
            float m10 = win[1][0] + wr[0];
            float m11 = win[1][1] + wr[0];
            #pragma unroll
            for (int t = 1; t < 25; t++) {
                const int du = t / 5, dv = t % 5;
                const float w = wr[t];
                m00 = fminf(m00, win[du][dv]         + w);
                m01 = fminf(m01, win[du][dv + 1]     + w);
                m10 = fminf(m10, win[du + 1][dv]     + w);
                m11 = fminf(m11, win[du + 1][dv + 1] + w);
            }
            g_p1[(b * 6 + 3 * cg + cc) * 224 + i * 16 + j] =
                0.25f * ((m00 + m01) + (m10 + m11));
        }
    }
}

// ---------------------------------------------------------------------------
// Kernel B: max-plus conv2 (C=6 -> O=16, k=5) + 2x2 avgpool.
// grid (2, Bh): CTA = 8 output channels of one image; thread = (ocp, sp),
// computes channels ocp and ocp+8 sharing the window.
// ---------------------------------------------------------------------------
__global__ void __launch_bounds__(224)
conv2_kernel(const float* __restrict__ w2, int b0)
{
    const int og = blockIdx.x, b = blockIdx.y + b0;
    const int tid = threadIdx.x;

    __shared__ __align__(16) float p1s[6 * 14 * 16];  // 1344
    __shared__ __align__(16) float ws[8 * 6 * 28];    // 1344

    const float* p1b = g_p1 + b * 1344;
    for (int i = tid; i < 1344; i += 224) p1s[i] = p1b[i];
    for (int i = tid; i < 1200; i += 224) {
        int f = i / 25, t = i % 25;
        ws[f * 28 + t] = w2[og * 1200 + i];
    }
    __syncthreads();

    if (tid < 200) {
        const int ocp = tid / 25, sp = tid % 25;
        const int i = sp / 5, j = sp % 5;
        const int wbase = ocp * 6 * 28;
        const int pbase = i * 32 + 2 * j;

        float acc0 = 0.0f, acc1 = 0.0f;
        #pragma unroll 1
        for (int c = 0; c < 6; c++) {
            float win[6][6];
            #pragma unroll
            for (int u = 0; u < 6; u++) {
                const float2* r = (const float2*)&p1s[c * 224 + pbase + u * 16];
                float2 a = r[0], bb = r[1], c2 = r[2];
                win[u][0] = a.x;  win[u][1] = a.y;
                win[u][2] = bb.x; win[u][3] = bb.y;
                win[u][4] = c2.x; win[u][5] = c2.y;
            }

            float wr0[25], wr1[25];
            {
                const float4* wq0 = (const float4*)&ws[wbase + c * 28];
                #pragma unroll
                for (int q = 0; q < 6; q++) {
                    float4 v = wq0[q];
                    wr0[4 * q]     = v.x; wr0[4 * q + 1] = v.y;
                    wr0[4 * q + 2] = v.z; wr0[4 * q + 3] = v.w;
                }
                wr0[24] = ws[wbase + c * 28 + 24];
            }

            // second channel's weights for ocp+8 are NOT in this CTA's ws if
            // og selects 8 contiguous channels; og*8..og*8+7, so channel pair
            // within CTA: use ocp and ocp+4? No: CTA has channels og*8+0..7,
            // thread handles ocp (0..7) only -> single channel per thread,
            // acc1 handles ocp's second quadrant set? -- keep two-channel
            // scheme: pair (ocp, ocp+4) both inside this CTA when using 100
            // threads... Simpler: thread handles channels og*8+ocp with
            // TWO spatial outputs? Revert: one channel per thread, two
            // accumulator chains come from quadrants only.
            float m00 = win[0][0] + wr0[0];
            float m01 = win[0][1] + wr0[0];
            float m10 = win[1][0] + wr0[0];
            float m11 = win[1][1] + wr0[0];
            #pragma unroll
            for (int t = 1; t < 25; t++) {
                const int du = t / 5, dv = t % 5;
                const float w = wr0[t];
                m00 = fmaxf(m00, win[du][dv]         + w);
                m01 = fmaxf(m01, win[du][dv + 1]     + w);
                m10 = fmaxf(m10, win[du + 1][dv]     + w);
                m11 = fmaxf(m11, win[du + 1][dv + 1] + w);
            }
            acc0 += (m00 + m01) + (m10 + m11);
            (void)acc1;
        }
        g_p2[b * 400 + (og * 8 + ocp) * 25 + sp] = 0.25f * acc0;
    }
}

// ---------------------------------------------------------------------------
// Kernel C: FC stack. grid Bh/2, 512 threads, 2 images per CTA, float4 loads.
// ---------------------------------------------------------------------------
__global__ void __launch_bounds__(512)
fc_kernel(const float* __restrict__ fw1, const float* __restrict__ fb1,
          const float* __restrict__ fw2, const float* __restrict__ fb2,
          const float* __restrict__ fw3, const float* __restrict__ fb3,
          float* __restrict__ out, int bg0)
{
    const int bg = blockIdx.x + bg0;
    const int tid = threadIdx.x;
    const int warp = tid >> 5, lane = tid & 31;

    __shared__ __align__(16) float x[2][400];
    __shared__ __align__(16) float h1[2][120];
    __shared__ __align__(16) float h2[2][84];

    for (int i = tid; i < 800; i += 512)
        x[i / 400][i % 400] = g_p2[bg * 800 + i];
    __syncthreads();

    // fc1: 400 -> 120, relu. 120 tasks = (img, out-pair).
    for (int t = warp; t < 120; t += 16) {
        const int img = t & 1, oo = t >> 1;
        const int o0 = 2 * oo, o1 = o0 + 1;
        const float4* wa = (const float4*)(fw1 + o0 * 400);
        const float4* wb = (const float4*)(fw1 + o1 * 400);
        const float4* xv = (const float4*)x[img];
        float sa = 0.0f, sb = 0.0f;
        #pragma unroll
        for (int k = 0; k < 3; k++) {
            const int i4 = lane + 32 * k;
            float4 v = xv[i4], a = wa[i4], c = wb[i4];
            sa = fmaf(v.x, a.x, sa); sa = fmaf(v.y, a.y, sa);
            sa = fmaf(v.z, a.z, sa); sa = fmaf(v.w, a.w, sa);
            sb = fmaf(v.x, c.x, sb); sb = fmaf(v.y, c.y, sb);
            sb = fmaf(v.z, c.z, sb); sb = fmaf(v.w, c.w, sb);
        }
        if (lane < 4) {
            const int i4 = 96 + lane;
            float4 v = xv[i4], a = wa[i4], c = wb[i4];
            sa = fmaf(v.x, a.x, sa); sa = fmaf(v.y, a.y, sa);
            sa = fmaf(v.z, a.z, sa); sa = fmaf(v.w, a.w, sa);
            sb = fmaf(v.x, c.x, sb); sb = fmaf(v.y, c.y, sb);
            sb = fmaf(v.z, c.z, sb); sb = fmaf(v.w, c.w, sb);
        }
        #pragma unroll
        for (int off = 16; off; off >>= 1) {
            sa += __shfl_xor_sync(0xffffffffu, sa, off);
            sb += __shfl_xor_sync(0xffffffffu, sb, off);
        }
        if (lane == 0) {
            h1[img][o0] = fmaxf(sa + fb1[o0], 0.0f);
            h1[img][o1] = fmaxf(sb + fb1[o1], 0.0f);
        }
    }
    __syncthreads();

    // fc2: 120 -> 84, relu.
    for (int t = warp; t < 84; t += 16) {
        const int img = t & 1, oo = t >> 1;
        const int o0 = 2 * oo, o1 = o0 + 1;
        const float4* wa = (const float4*)(fw2 + o0 * 120);
        const float4* wb = (const float4*)(fw2 + o1 * 120);
        const float4* xv = (const float4*)h1[img];
        float sa = 0.0f, sb = 0.0f;
        if (lane < 30) {
            float4 v = xv[lane], a = wa[lane], c = wb[lane];
            sa = fmaf(v.x, a.x, sa); sa = fmaf(v.y, a.y, sa);
            sa = fmaf(v.z, a.z, sa); sa = fmaf(v.w, a.w, sa);
            sb = fmaf(v.x, c.x, sb); sb = fmaf(v.y, c.y, sb);
            sb = fmaf(v.z, c.z, sb); sb = fmaf(v.w, c.w, sb);
        }
        #pragma unroll
        for (int off = 16; off; off >>= 1) {
            sa += __shfl_xor_sync(0xffffffffu, sa, off);
            sb += __shfl_xor_sync(0xffffffffu, sb, off);
        }
        if (lane == 0) {
            h2[img][o0] = fmaxf(sa + fb2[o0], 0.0f);
            h2[img][o1] = fmaxf(sb + fb2[o1], 0.0f);
        }
    }
    __syncthreads();

    // fc3: 84 -> 10.
    for (int t = warp; t < 20; t += 16) {
        const int img = t & 1, o = t >> 1;
        const float4* wr = (const float4*)(fw3 + o * 84);
        const float4* xv = (const float4*)h2[img];
        float s = 0.0f;
        if (lane < 21) {
            float4 v = xv[lane], a = wr[lane];
            s = fmaf(v.x, a.x, s); s = fmaf(v.y, a.y, s);
            s = fmaf(v.z, a.z, s); s = fmaf(v.w, a.w, s);
        }
        #pragma unroll
        for (int off = 16; off; off >>= 1) s += __shfl_xor_sync(0xffffffffu, s, off);
        if (lane == 0) out[(2 * bg + img) * 10 + o] = s + fb3[o];
    }
}

extern "C" void kernel_launch(void* const* d_in, const int* in_sizes, int n_in,
                              void* d_out, int out_size)
{
    const float* input = (const float*)d_in[0];
    const float* w1    = (const float*)d_in[1];
    const float* w2    = (const float*)d_in[2];
    const float* fw1   = (const float*)d_in[3];
    const float* fb1   = (const float*)d_in[4];
    const float* fw2   = (const float*)d_in[5];
    const float* fb2   = (const float*)d_in[6];
    const float* fw3   = (const float*)d_in[7];
    const float* fb3   = (const float*)d_in[8];

    const int B  = in_sizes[0] / 784;  // 256
    const int Bh = B / 2;

    // One-time side-stream + events (resource init only; identical work on
    // every call, so the launch remains deterministic and capturable).
    static cudaStream_t s2 = nullptr;
    static cudaEvent_t  e0 = nullptr, e1 = nullptr;
    if (s2 == nullptr) {
        cudaStreamCreateWithFlags(&s2, cudaStreamNonBlocking);
        cudaEventCreateWithFlags(&e0, cudaEventDisableTiming);
        cudaEventCreateWithFlags(&e1, cudaEventDisableTiming);
    }

    float* out = (float*)d_out;

    // Fork: half A on the (capture) null stream, half B on s2.
    cudaEventRecord(e0, 0);
    cudaStreamWaitEvent(s2, e0, 0);

    conv1_kernel<<<dim3(2, Bh), 224, 0, 0>>>(input, w1, 0);
    conv1_kernel<<<dim3(2, Bh), 224, 0, s2>>>(input, w1, Bh);

    conv2_kernel<<<dim3(2, Bh), 224, 0, 0>>>(w2, 0);
    conv2_kernel<<<dim3(2, Bh), 224, 0, s2>>>(w2, Bh);

    fc_kernel<<<Bh / 2, 512, 0, 0>>>(fw1, fb1, fw2, fb2, fw3, fb3, out, 0);
    fc_kernel<<<Bh / 2, 512, 0, s2>>>(fw1, fb1, fw2, fb2, fw3, fb3, out, Bh / 2);

    // Join.
    cudaEventRecord(e1, s2);
    cudaStreamWaitEvent(0, e1, 0);
}

// round 6
// speedup vs baseline: 1.8286x; 1.8286x over previous
#include <cuda_runtime.h>

// TropicalLeNet fully fused, ONE kernel launch, one wave:
// grid = B (256), 512 threads/CTA, 2 CTAs/SM resident.
// All intermediates in shared memory; no global scratch.

__global__ void __launch_bounds__(512, 2)
lenet_kernel(const float* __restrict__ input,
             const float* __restrict__ w1,
             const float* __restrict__ w2,
             const float* __restrict__ fw1, const float* __restrict__ fb1,
             const float* __restrict__ fw2, const float* __restrict__ fb2,
             const float* __restrict__ fw3, const float* __restrict__ fb3,
             float* __restrict__ out)
{
    const int b   = blockIdx.x;
    const int tid = threadIdx.x;
    const int warp = tid >> 5, lane = tid & 31;

    __shared__ __align__(16) float xp[32 * 32];       // padded input (rows=128B)
    __shared__ __align__(16) float w1s[6 * 28];       // filters padded to 28
    __shared__ __align__(16) float w2s[16 * 6 * 28];  // 2688
    __shared__ __align__(16) float p1s[6 * 14 * 16];  // conv1+pool out
    __shared__ __align__(16) float p2s[400];          // conv2+pool out (flatten)
    __shared__ __align__(16) float h1[120];
    __shared__ __align__(16) float h2[84];

    // ---- stage 0: stage input (zero-padded) + conv weights ----
    {
        const float* inb = input + b * 784;
        #pragma unroll
        for (int k = 0; k < 2; k++) {
            int i = tid + 512 * k;
            int h = i >> 5, w = i & 31;
            bool in = (h >= 2) && (h < 30) && (w >= 2) && (w < 30);
            xp[i] = in ? inb[(h - 2) * 28 + (w - 2)] : 0.0f;
        }
        if (tid < 150) w1s[(tid / 25) * 28 + tid % 25] = w1[tid];
        for (int i = tid; i < 2400; i += 512) {
            int f = i / 25, t = i % 25;
            w2s[f * 28 + t] = w2[i];
        }
    }
    __syncthreads();

    // ---- stage 1: min-plus conv1 + avgpool -> p1s[6][14][16] ----
    // 392 threads: sp = tid%196, cg = tid/196 in {0,1} -> channels 3cg..3cg+2.
    if (tid < 392) {
        const int sp = tid % 196, cg = tid / 196;
        const int i = sp / 14, j = sp % 14;
        const int base = i * 64 + 2 * j;

        float win[6][6];
        #pragma unroll
        for (int u = 0; u < 6; u++) {
            const float2* r = (const float2*)&xp[base + u * 32];
            float2 a = r[0], bb = r[1], c2 = r[2];
            win[u][0] = a.x;  win[u][1] = a.y;
            win[u][2] = bb.x; win[u][3] = bb.y;
            win[u][4] = c2.x; win[u][5] = c2.y;
        }

        #pragma unroll 1
        for (int cc = 0; cc < 3; cc++) {
            const float* wr = &w1s[(3 * cg + cc) * 28];   // uniform broadcast
            float m00 = win[0][0] + wr[0];
            float m01 = win[0][1] + wr[0];
            float m10 = win[1][0] + wr[0];
            float m11 = win[1][1] + wr[0];
            #pragma unroll
            for (int t = 1; t < 25; t++) {
                const int du = t / 5, dv = t % 5;
                const float w = wr[t];
                m00 = fminf(m00, win[du][dv]         + w);
                m01 = fminf(m01, win[du][dv + 1]     + w);
                m10 = fminf(m10, win[du + 1][dv]     + w);
                m11 = fminf(m11, win[du + 1][dv + 1] + w);
            }
            p1s[(3 * cg + cc) * 224 + i * 16 + j] =
                0.25f * ((m00 + m01) + (m10 + m11));
        }
    }
    __syncthreads();

    // ---- stage 2: max-plus conv2 + avgpool -> p2s[400] ----
    // 400 threads: oc = tid/25, sp = tid%25.
    if (tid < 400) {
        const int oc = tid / 25, sp = tid % 25;
        const int i = sp / 5, j = sp % 5;
        const int pbase = i * 32 + 2 * j;

        float acc = 0.0f;
        #pragma unroll 1
        for (int c = 0; c < 6; c++) {
            float win[6][6];
            #pragma unroll
            for (int u = 0; u < 6; u++) {
                const float2* r = (const float2*)&p1s[c * 224 + pbase + u * 16];
                float2 a = r[0], bb = r[1], c2 = r[2];
                win[u][0] = a.x;  win[u][1] = a.y;
                win[u][2] = bb.x; win[u][3] = bb.y;
                win[u][4] = c2.x; win[u][5] = c2.y;
            }

            const float* wr = &w2s[(oc * 6 + c) * 28];    // ~2-way broadcast
            float m00 = win[0][0] + wr[0];
            float m01 = win[0][1] + wr[0];
            float m10 = win[1][0] + wr[0];
            float m11 = win[1][1] + wr[0];
            #pragma unroll
            for (int t = 1; t < 25; t++) {
                const int du = t / 5, dv = t % 5;
                const float w = wr[t];
                m00 = fmaxf(m00, win[du][dv]         + w);
                m01 = fmaxf(m01, win[du][dv + 1]     + w);
                m10 = fmaxf(m10, win[du + 1][dv]     + w);
                m11 = fmaxf(m11, win[du + 1][dv + 1] + w);
            }
            acc += (m00 + m01) + (m10 + m11);
        }
        p2s[oc * 25 + sp] = 0.25f * acc;
    }
    __syncthreads();

    // ---- stage 3: fc1 400 -> 120, relu. 60 output-pair tasks over 16 warps.
    for (int t = warp; t < 60; t += 16) {
        const int o0 = 2 * t, o1 = o0 + 1;
        const float4* wa = (const float4*)(fw1 + o0 * 400);
        const float4* wb = (const float4*)(fw1 + o1 * 400);
        const float4* xv = (const float4*)p2s;
        float sa = 0.0f, sb = 0.0f;
        #pragma unroll
        for (int k = 0; k < 3; k++) {
            const int i4 = lane + 32 * k;
            float4 v = xv[i4], a = wa[i4], c = wb[i4];
            sa = fmaf(v.x, a.x, sa); sa = fmaf(v.y, a.y, sa);
            sa = fmaf(v.z, a.z, sa); sa = fmaf(v.w, a.w, sa);
            sb = fmaf(v.x, c.x, sb); sb = fmaf(v.y, c.y, sb);
            sb = fmaf(v.z, c.z, sb); sb = fmaf(v.w, c.w, sb);
        }
        if (lane < 4) {
            const int i4 = 96 + lane;
            float4 v = xv[i4], a = wa[i4], c = wb[i4];
            sa = fmaf(v.x, a.x, sa); sa = fmaf(v.y, a.y, sa);
            sa = fmaf(v.z, a.z, sa); sa = fmaf(v.w, a.w, sa);
            sb = fmaf(v.x, c.x, sb); sb = fmaf(v.y, c.y, sb);
            sb = fmaf(v.z, c.z, sb); sb = fmaf(v.w, c.w, sb);
        }
        #pragma unroll
        for (int off = 16; off; off >>= 1) {
            sa += __shfl_xor_sync(0xffffffffu, sa, off);
            sb += __shfl_xor_sync(0xffffffffu, sb, off);
        }
        if (lane == 0) {
            h1[o0] = fmaxf(sa + fb1[o0], 0.0f);
            h1[o1] = fmaxf(sb + fb1[o1], 0.0f);
        }
    }
    __syncthreads();

    // ---- fc2: 120 -> 84, relu. 42 tasks; 30 float4/row, lanes 0..29.
    for (int t = warp; t < 42; t += 16) {
        const int o0 = 2 * t, o1 = o0 + 1;
        const float4* wa = (const float4*)(fw2 + o0 * 120);
        const float4* wb = (const float4*)(fw2 + o1 * 120);
        const float4* xv = (const float4*)h1;
        float sa = 0.0f, sb = 0.0f;
        if (lane < 30) {
            float4 v = xv[lane], a = wa[lane], c = wb[lane];
            sa = fmaf(v.x, a.x, sa); sa = fmaf(v.y, a.y, sa);
            sa = fmaf(v.z, a.z, sa); sa = fmaf(v.w, a.w, sa);
            sb = fmaf(v.x, c.x, sb); sb = fmaf(v.y, c.y, sb);
            sb = fmaf(v.z, c.z, sb); sb = fmaf(v.w, c.w, sb);
        }
        #pragma unroll
        for (int off = 16; off; off >>= 1) {
            sa += __shfl_xor_sync(0xffffffffu, sa, off);
            sb += __shfl_xor_sync(0xffffffffu, sb, off);
        }
        if (lane == 0) {
            h2[o0] = fmaxf(sa + fb2[o0], 0.0f);
            h2[o1] = fmaxf(sb + fb2[o1], 0.0f);
        }
    }
    __syncthreads();

    // ---- fc3: 84 -> 10. warps 0..9, one output each; 21 float4/row.
    if (warp < 10) {
        const int o = warp;
        const float4* wr = (const float4*)(fw3 + o * 84);
        const float4* xv = (const float4*)h2;
        float s = 0.0f;
        if (lane < 21) {
            float4 v = xv[lane], a = wr[lane];
            s = fmaf(v.x, a.x, s); s = fmaf(v.y, a.y, s);
            s = fmaf(v.z, a.z, s); s = fmaf(v.w, a.w, s);
        }
        #pragma unroll
        for (int off = 16; off; off >>= 1) s += __shfl_xor_sync(0xffffffffu, s, off);
        if (lane == 0) out[b * 10 + o] = s + fb3[o];
    }
}

extern "C" void kernel_launch(void* const* d_in, const int* in_sizes, int n_in,
                              void* d_out, int out_size)
{
    const float* input = (const float*)d_in[0];
    const float* w1    = (const float*)d_in[1];
    const float* w2    = (const float*)d_in[2];
    const float* fw1   = (const float*)d_in[3];
    const float* fb1   = (const float*)d_in[4];
    const float* fw2   = (const float*)d_in[5];
    const float* fb2   = (const float*)d_in[6];
    const float* fw3   = (const float*)d_in[7];
    const float* fb3   = (const float*)d_in[8];

    const int B = in_sizes[0] / 784;  // 256

    lenet_kernel<<<B, 512>>>(input, w1, w2, fw1, fb1, fw2, fb2, fw3, fb3,
                             (float*)d_out);
}

// round 7
// speedup vs baseline: 2.2819x; 1.2479x over previous
#include <cuda_runtime.h>

// TropicalLeNet fully fused, one launch, one wave. Bank-conflict-free layouts:
//   xp  row stride 34  (conv1 window loads degree <=2)
//   p1  row stride 22, channel stride 320 (conv2 window loads degree <=2)
//   conv2 thread map (oc = tid&15, sp = tid>>4): window loads are 2-address
//   broadcasts; weight reads hit 16 distinct banks (stride 174 per oc).

__global__ void __launch_bounds__(512, 2)
lenet_kernel(const float* __restrict__ input,
             const float* __restrict__ w1,
             const float* __restrict__ w2,
             const float* __restrict__ fw1, const float* __restrict__ fb1,
             const float* __restrict__ fw2, const float* __restrict__ fb2,
             const float* __restrict__ fw3, const float* __restrict__ fb3,
             float* __restrict__ out)
{
    const int b   = blockIdx.x;
    const int tid = threadIdx.x;
    const int warp = tid >> 5, lane = tid & 31;

    __shared__ __align__(16) float xp[32 * 34];       // padded input, stride 34
    __shared__ __align__(16) float w1s[6 * 28];
    __shared__ __align__(16) float w2s[16 * 174];     // [oc]*174 + [c]*29 + t
    __shared__ __align__(16) float p1s[6 * 320];      // [c]*320 + r*22 + col
    __shared__ __align__(16) float p2s[400];
    __shared__ __align__(16) float h1[120];
    __shared__ __align__(16) float h2[84];

    // ---- stage 0: stage input (zero-padded) + conv weights ----
    {
        const float* inb = input + b * 784;
        #pragma unroll
        for (int k = 0; k < 2; k++) {
            int i = tid + 512 * k;
            int h = i >> 5, w = i & 31;
            bool in = (h >= 2) && (h < 30) && (w >= 2) && (w < 30);
            xp[h * 34 + w] = in ? inb[(h - 2) * 28 + (w - 2)] : 0.0f;
        }
        if (tid < 150) w1s[(tid / 25) * 28 + tid % 25] = w1[tid];
        for (int i = tid; i < 2400; i += 512) {
            int f = i / 25, t = i % 25;           // f = oc*6 + c
            w2s[(f / 6) * 174 + (f % 6) * 29 + t] = w2[i];
        }
    }
    __syncthreads();

    // ---- stage 1: min-plus conv1 + avgpool -> p1s ----
    // 392 threads: sp = tid%196, cg = tid/196 -> channels 3cg..3cg+2.
    if (tid < 392) {
        const int sp = tid % 196, cg = tid / 196;
        const int i = sp / 14, j = sp % 14;
        const int base = i * 68 + 2 * j;          // (2i)*34 + 2j (even)

        float win[6][6];
        #pragma unroll
        for (int u = 0; u < 6; u++) {
            const float2* r = (const float2*)&xp[base + u * 34];
            float2 a = r[0], bb = r[1], c2 = r[2];
            win[u][0] = a.x;  win[u][1] = a.y;
            win[u][2] = bb.x; win[u][3] = bb.y;
            win[u][4] = c2.x; win[u][5] = c2.y;
        }

        #pragma unroll 1
        for (int cc = 0; cc < 3; cc++) {
            const float* wr = &w1s[(3 * cg + cc) * 28];   // uniform broadcast
            float m00 = win[0][0] + wr[0];
            float m01 = win[0][1] + wr[0];
            float m10 = win[1][0] + wr[0];
            float m11 = win[1][1] + wr[0];
            #pragma unroll
            for (int t = 1; t < 25; t++) {
                const int du = t / 5, dv = t % 5;
                const float w = wr[t];
                m00 = fminf(m00, win[du][dv]         + w);
                m01 = fminf(m01, win[du][dv + 1]     + w);
                m10 = fminf(m10, win[du + 1][dv]     + w);
                m11 = fminf(m11, win[du + 1][dv + 1] + w);
            }
            p1s[(3 * cg + cc) * 320 + i * 22 + j] =
                0.25f * ((m00 + m01) + (m10 + m11));
        }
    }
    __syncthreads();

    // ---- stage 2: max-plus conv2 + avgpool -> p2s[400] ----
    // oc = tid&15, sp = tid>>4 (active sp<25): warp = 16 oc x 2 sp.
    {
        const int oc = tid & 15, sp = tid >> 4;
        if (sp < 25) {
            const int i = sp / 5, j = sp % 5;
            const int pbase = i * 44 + 2 * j;     // (2i)*22 + 2j (even)
            const float* wsoc = &w2s[oc * 174];

            float acc = 0.0f;
            #pragma unroll 1
            for (int c = 0; c < 6; c++) {
                float win[6][6];
                #pragma unroll
                for (int u = 0; u < 6; u++) {
                    const float2* r =
                        (const float2*)&p1s[c * 320 + pbase + u * 22];
                    float2 a = r[0], bb = r[1], c2 = r[2];
                    win[u][0] = a.x;  win[u][1] = a.y;
                    win[u][2] = bb.x; win[u][3] = bb.y;
                    win[u][4] = c2.x; win[u][5] = c2.y;
                }

                const float* wr = &wsoc[c * 29];  // 16 distinct banks/warp
                float m00 = win[0][0] + wr[0];
                float m01 = win[0][1] + wr[0];
                float m10 = win[1][0] + wr[0];
                float m11 = win[1][1] + wr[0];
                #pragma unroll
                for (int t = 1; t < 25; t++) {
                    const int du = t / 5, dv = t % 5;
                    const float w = wr[t];
                    m00 = fmaxf(m00, win[du][dv]         + w);
                    m01 = fmaxf(m01, win[du][dv + 1]     + w);
                    m10 = fmaxf(m10, win[du + 1][dv]     + w);
                    m11 = fmaxf(m11, win[du + 1][dv + 1] + w);
                }
                acc += (m00 + m01) + (m10 + m11);
            }
            p2s[oc * 25 + sp] = 0.25f * acc;
        }
    }
    __syncthreads();

    // ---- fc1: 400 -> 120, relu. 60 output-pair tasks over 16 warps.
    for (int t = warp; t < 60; t += 16) {
        const int o0 = 2 * t, o1 = o0 + 1;
        const float4* wa = (const float4*)(fw1 + o0 * 400);
        const float4* wb = (const float4*)(fw1 + o1 * 400);
        const float4* xv = (const float4*)p2s;
        float sa = 0.0f, sb = 0.0f;
        #pragma unroll
        for (int k = 0; k < 3; k++) {
            const int i4 = lane + 32 * k;
            float4 v = xv[i4], a = wa[i4], c = wb[i4];
            sa = fmaf(v.x, a.x, sa); sa = fmaf(v.y, a.y, sa);
            sa = fmaf(v.z, a.z, sa); sa = fmaf(v.w, a.w, sa);
            sb = fmaf(v.x, c.x, sb); sb = fmaf(v.y, c.y, sb);
            sb = fmaf(v.z, c.z, sb); sb = fmaf(v.w, c.w, sb);
        }
        if (lane < 4) {
            const int i4 = 96 + lane;
            float4 v = xv[i4], a = wa[i4], c = wb[i4];
            sa = fmaf(v.x, a.x, sa); sa = fmaf(v.y, a.y, sa);
            sa = fmaf(v.z, a.z, sa); sa = fmaf(v.w, a.w, sa);
            sb = fmaf(v.x, c.x, sb); sb = fmaf(v.y, c.y, sb);
            sb = fmaf(v.z, c.z, sb); sb = fmaf(v.w, c.w, sb);
        }
        #pragma unroll
        for (int off = 16; off; off >>= 1) {
            sa += __shfl_xor_sync(0xffffffffu, sa, off);
            sb += __shfl_xor_sync(0xffffffffu, sb, off);
        }
        if (lane == 0) {
            h1[o0] = fmaxf(sa + fb1[o0], 0.0f);
            h1[o1] = fmaxf(sb + fb1[o1], 0.0f);
        }
    }
    __syncthreads();

    // ---- fc2: 120 -> 84, relu. 42 tasks; 30 float4/row.
    for (int t = warp; t < 42; t += 16) {
        const int o0 = 2 * t, o1 = o0 + 1;
        const float4* wa = (const float4*)(fw2 + o0 * 120);
        const float4* wb = (const float4*)(fw2 + o1 * 120);
        const float4* xv = (const float4*)h1;
        float sa = 0.0f, sb = 0.0f;
        if (lane < 30) {
            float4 v = xv[lane], a = wa[lane], c = wb[lane];
            sa = fmaf(v.x, a.x, sa); sa = fmaf(v.y, a.y, sa);
            sa = fmaf(v.z, a.z, sa); sa = fmaf(v.w, a.w, sa);
            sb = fmaf(v.x, c.x, sb); sb = fmaf(v.y, c.y, sb);
            sb = fmaf(v.z, c.z, sb); sb = fmaf(v.w, c.w, sb);
        }
        #pragma unroll
        for (int off = 16; off; off >>= 1) {
            sa += __shfl_xor_sync(0xffffffffu, sa, off);
            sb += __shfl_xor_sync(0xffffffffu, sb, off);
        }
        if (lane == 0) {
            h2[o0] = fmaxf(sa + fb2[o0], 0.0f);
            h2[o1] = fmaxf(sb + fb2[o1], 0.0f);
        }
    }
    __syncthreads();

    // ---- fc3: 84 -> 10. warps 0..9, one output each.
    if (warp < 10) {
        const int o = warp;
        const float4* wr = (const float4*)(fw3 + o * 84);
        const float4* xv = (const float4*)h2;
        float s = 0.0f;
        if (lane < 21) {
            float4 v = xv[lane], a = wr[lane];
            s = fmaf(v.x, a.x, s); s = fmaf(v.y, a.y, s);
            s = fmaf(v.z, a.z, s); s = fmaf(v.w, a.w, s);
        }
        #pragma unroll
        for (int off = 16; off; off >>= 1) s += __shfl_xor_sync(0xffffffffu, s, off);
        if (lane == 0) out[b * 10 + o] = s + fb3[o];
    }
}

extern "C" void kernel_launch(void* const* d_in, const int* in_sizes, int n_in,
                              void* d_out, int out_size)
{
    const float* input = (const float*)d_in[0];
    const float* w1    = (const float*)d_in[1];
    const float* w2    = (const float*)d_in[2];
    const float* fw1   = (const float*)d_in[3];
    const float* fb1   = (const float*)d_in[4];
    const float* fw2   = (const float*)d_in[5];
    const float* fb2   = (const float*)d_in[6];
    const float* fw3   = (const float*)d_in[7];
    const float* fb3   = (const float*)d_in[8];

    const int B = in_sizes[0] / 784;  // 256

    lenet_kernel<<<B, 512>>>(input, w1, w2, fw1, fb1, fw2, fb2, fw3, fb3,
                             (float*)d_out);
}